// round 5
// baseline (speedup 1.0000x reference)
#include <cuda_runtime.h>
#include <cuda_fp16.h>
#include <cstdint>

#define NN 100000
#define NE 1600000

// ---------------- scratch ----------------
__device__ __half g_h [NN * 128];   // node features fp16
__device__ __half g_hl[NN * 128];   // h @ Wl fp16 (gathered operand)
__device__ __half g_hr[NN * 128];   // h @ Wr fp16 (skip path)
__device__ __half g_w2[128 * 256];  // packed fp16 [K][Wl|Wr]
__device__ __half g_w3[128 * 64];
__device__ int    g_cnt[NN];
__device__ int    g_rowptr[NN + 1];
__device__ int    g_cursor[NN];
__device__ int    g_csrc[NE];
__device__ unsigned g_state[128];   // lookback scan state

// ---------------- mma helpers ----------------
__device__ __forceinline__ uint32_t smem_u32(const void* p) {
    return (uint32_t)__cvta_generic_to_shared(p);
}
__device__ __forceinline__ void ldsm_x4(uint32_t& r0, uint32_t& r1, uint32_t& r2, uint32_t& r3, uint32_t a) {
    asm volatile("ldmatrix.sync.aligned.m8n8.x4.shared.b16 {%0,%1,%2,%3},[%4];"
                 : "=r"(r0), "=r"(r1), "=r"(r2), "=r"(r3) : "r"(a));
}
__device__ __forceinline__ void ldsm_x2t(uint32_t& r0, uint32_t& r1, uint32_t a) {
    asm volatile("ldmatrix.sync.aligned.m8n8.x2.trans.shared.b16 {%0,%1},[%2];"
                 : "=r"(r0), "=r"(r1) : "r"(a));
}
__device__ __forceinline__ void mma16816(float* c, uint32_t a0, uint32_t a1, uint32_t a2, uint32_t a3,
                                         uint32_t b0, uint32_t b1) {
    asm volatile("mma.sync.aligned.m16n8k16.row.col.f32.f16.f16.f32 "
                 "{%0,%1,%2,%3},{%4,%5,%6,%7},{%8,%9},{%0,%1,%2,%3};"
                 : "+f"(c[0]), "+f"(c[1]), "+f"(c[2]), "+f"(c[3])
                 : "r"(a0), "r"(a1), "r"(a2), "r"(a3), "r"(b0), "r"(b1));
}

// ---------------- count + weight pack + state zero (one kernel) ----------------
__global__ void k_count(const int* __restrict__ ei, int* __restrict__ cnt, int E,
                        const float* Wl2, const float* Wr2, const float* Wl3, const float* Wr3,
                        __half* w2, __half* w3, unsigned* state) {
    int e = blockIdx.x * blockDim.x + threadIdx.x;
    if (e < E) atomicAdd(&cnt[ei[E + e]], 1);
    // fold: zero lookback state
    if (blockIdx.x == 0 && threadIdx.x < 128) state[threadIdx.x] = 0u;
    // fold: weight pack (first 160 blocks cover 40960 elements)
    int i = e;
    if (i < 32768) {
        int k = i / 256, j = i % 256;
        float v = (j < 128) ? Wl2[k * 128 + j] : Wr2[k * 128 + j - 128];
        w2[i] = __float2half_rn(v);
    } else if (i < 40960) {
        int q = i - 32768;
        int k = q / 64, j = q % 64;
        float v = (j < 32) ? Wl3[k * 32 + j] : Wr3[k * 32 + j - 32];
        w3[q] = __float2half_rn(v);
    }
}

// ---------------- decoupled-lookback exclusive scan (1 kernel) ----------------
// 1024 elements per block, 256 threads x 4. Writes rowptr (inclusive at idx+1) and cursor (exclusive).
__global__ void k_scan_lb(const int* __restrict__ cnt, volatile unsigned* state,
                          int* __restrict__ rowptr, int* __restrict__ cursor, int n) {
    __shared__ int ws[8];
    __shared__ int s_pref;
    int bid = blockIdx.x;
    int base = bid * 1024 + threadIdx.x * 4;
    int c[4];
#pragma unroll
    for (int q = 0; q < 4; q++) { int idx = base + q; c[q] = (idx < n) ? cnt[idx] : 0; }
    int s1 = c[0], s2 = s1 + c[1], s3 = s2 + c[2], s4 = s3 + c[3];
    int lane = threadIdx.x & 31, w = threadIdx.x >> 5;
    int v = s4;
#pragma unroll
    for (int d = 1; d < 32; d <<= 1) {
        int u = __shfl_up_sync(0xffffffffu, v, d);
        if (lane >= d) v += u;
    }
    int texcl = v - s4;
    if (lane == 31) ws[w] = v;
    __syncthreads();
    if (threadIdx.x == 0) {
        int run = 0;
#pragma unroll
        for (int i = 0; i < 8; i++) { int t = ws[i]; ws[i] = run; run += t; }
        if (bid == 0) {
            state[0] = ((unsigned)run << 2) | 2u;   // PREFIX
            __threadfence();
            s_pref = 0;
        } else {
            state[bid] = ((unsigned)run << 2) | 1u; // AGGREGATE
            __threadfence();
            int pref = 0;
            int j = bid - 1;
            while (true) {
                unsigned st = state[j];
                unsigned mode = st & 3u;
                if (mode == 0u) { __nanosleep(20); continue; }
                pref += (int)(st >> 2);
                if (mode == 2u) break;
                j--;
            }
            state[bid] = ((unsigned)(pref + run) << 2) | 2u;
            __threadfence();
            s_pref = pref;
        }
    }
    __syncthreads();
    int ofs = s_pref + ws[w] + texcl;
    int sv[4] = {s1, s2, s3, s4};
#pragma unroll
    for (int q = 0; q < 4; q++) {
        int idx = base + q;
        if (idx < n) {
            int val = ofs + sv[q];
            rowptr[idx + 1] = val;
            cursor[idx] = val - c[q];
        }
    }
    if (bid == 0 && threadIdx.x == 0) rowptr[0] = 0;
}

__global__ void k_fill(const int* __restrict__ ei, int* __restrict__ cursor,
                       int* __restrict__ csrc, int E) {
    int e = blockIdx.x * blockDim.x + threadIdx.x;
    if (e < E) {
        int s = ei[e], d = ei[E + e];
        int p = atomicAdd(&cursor[d], 1);
        csrc[p] = s;
    }
}

// ---------------- layer 1 ----------------
__global__ void k_layer1(const float* __restrict__ x, const int* __restrict__ rowptr,
                         const int* __restrict__ csrc,
                         const float* __restrict__ Wl, const float* __restrict__ bl,
                         const float* __restrict__ Wr,
                         __half* __restrict__ hout, int n) {
    __shared__ float sWl[256], sWr[256], sbl[128];
    for (int i = threadIdx.x; i < 256; i += blockDim.x) { sWl[i] = Wl[i]; sWr[i] = Wr[i]; }
    for (int i = threadIdx.x; i < 128; i += blockDim.x) sbl[i] = bl[i];
    __syncthreads();
    int gw = (blockIdx.x * blockDim.x + threadIdx.x) >> 5;
    int lane = threadIdx.x & 31;
    if (gw >= n) return;
    int rs = rowptr[gw], re = rowptr[gw + 1];
    float ax = 0.f, ay = 0.f;
    for (int t = rs + lane; t < re; t += 32) {
        int s = csrc[t];
        float2 v = *(const float2*)&x[2 * s];
        ax += v.x; ay += v.y;
    }
#pragma unroll
    for (int d = 16; d; d >>= 1) {
        ax += __shfl_xor_sync(0xffffffffu, ax, d);
        ay += __shfl_xor_sync(0xffffffffu, ay, d);
    }
    float dv = (float)(re - rs);
    float inv = 1.0f / fmaxf(dv, 1.0f);
    ax *= inv; ay *= inv;
    float2 xv = *(const float2*)&x[2 * gw];
    int j = lane * 4;
    float o0 = fmaxf(ax * sWl[j + 0] + ay * sWl[128 + j + 0] + sbl[j + 0] + xv.x * sWr[j + 0] + xv.y * sWr[128 + j + 0], 0.f);
    float o1 = fmaxf(ax * sWl[j + 1] + ay * sWl[128 + j + 1] + sbl[j + 1] + xv.x * sWr[j + 1] + xv.y * sWr[128 + j + 1], 0.f);
    float o2 = fmaxf(ax * sWl[j + 2] + ay * sWl[128 + j + 2] + sbl[j + 2] + xv.x * sWr[j + 2] + xv.y * sWr[128 + j + 2], 0.f);
    float o3 = fmaxf(ax * sWl[j + 3] + ay * sWl[128 + j + 3] + sbl[j + 3] + xv.x * sWr[j + 3] + xv.y * sWr[128 + j + 3], 0.f);
    __half2 p0 = __floats2half2_rn(o0, o1);
    __half2 p1 = __floats2half2_rn(o2, o3);
    uint2 v;
    v.x = *(unsigned*)&p0; v.y = *(unsigned*)&p1;
    *(uint2*)&hout[gw * 128 + j] = v;
}

// ---------------- tensor-core GEMM: [Cl | Cr] both fp16 ----------------
template <int K, int COUT, int WN>
__global__ void k_gemm_mma(const __half* __restrict__ A, const __half* __restrict__ W,
                           __half* __restrict__ Cl, __half* __restrict__ Cr, int n) {
    constexpr int BN = 2 * COUT;
    constexpr int NWN = BN / WN;
    constexpr int NW = 4 * NWN;
    constexpr int THREADS = NW * 32;
    constexpr int LDA = K + 8;
    constexpr int LDB = BN + 8;
    constexpr int NFN = WN / 8;
    extern __shared__ __half sm[];
    __half* As = sm;
    __half* Bs = sm + 128 * LDA;
    int tid = threadIdx.x;
    int row0 = blockIdx.x * 128;

    for (int i = tid; i < K * BN / 8; i += THREADS) {
        int f = i * 8;
        int k = f / BN, j = f % BN;
        *(uint4*)&Bs[k * LDB + j] = *(const uint4*)&W[f];
    }
    for (int i = tid; i < 128 * K / 8; i += THREADS) {
        int f = i * 8;
        int m = f / K, k = f % K;
        int row = row0 + m;
        uint4 v = make_uint4(0u, 0u, 0u, 0u);
        if (row < n) v = *(const uint4*)&A[row * K + k];
        *(uint4*)&As[m * LDA + k] = v;
    }
    __syncthreads();

    int wid = tid >> 5, lane = tid & 31;
    int wm = wid & 3, wn = wid >> 2;
    int m_base = wm * 32, n_base = wn * WN;

    float acc[2][NFN][4];
#pragma unroll
    for (int im = 0; im < 2; im++)
#pragma unroll
        for (int jn = 0; jn < NFN; jn++)
#pragma unroll
            for (int q = 0; q < 4; q++) acc[im][jn][q] = 0.f;

    int lr = lane & 15, lc = lane >> 4;
    uint32_t a_base0 = smem_u32(&As[(m_base + lr) * LDA]);
    uint32_t a_base1 = smem_u32(&As[(m_base + 16 + lr) * LDA]);
    uint32_t b_base = smem_u32(&Bs[lr * LDB + n_base]);

#pragma unroll
    for (int k0 = 0; k0 < K; k0 += 16) {
        uint32_t af[2][4];
        ldsm_x4(af[0][0], af[0][1], af[0][2], af[0][3], a_base0 + (k0 + lc * 8) * 2);
        ldsm_x4(af[1][0], af[1][1], af[1][2], af[1][3], a_base1 + (k0 + lc * 8) * 2);
        uint32_t bf[NFN][2];
#pragma unroll
        for (int jn = 0; jn < NFN; jn++)
            ldsm_x2t(bf[jn][0], bf[jn][1], b_base + (k0 * LDB + jn * 8) * 2);
#pragma unroll
        for (int im = 0; im < 2; im++)
#pragma unroll
            for (int jn = 0; jn < NFN; jn++)
                mma16816(acc[im][jn], af[im][0], af[im][1], af[im][2], af[im][3],
                         bf[jn][0], bf[jn][1]);
    }

    int quad = lane >> 2, t4 = lane & 3;
#pragma unroll
    for (int im = 0; im < 2; im++) {
#pragma unroll
        for (int jn = 0; jn < NFN; jn++) {
            int col = n_base + jn * 8 + t4 * 2;
            int r0 = row0 + m_base + im * 16 + quad;
            int r1 = r0 + 8;
            __half* C;
            int cc;
            if (col < COUT) { C = Cl; cc = col; }
            else            { C = Cr; cc = col - COUT; }
            if (r0 < n) {
                __half2 h = __floats2half2_rn(acc[im][jn][0], acc[im][jn][1]);
                *(__half2*)&C[r0 * COUT + cc] = h;
            }
            if (r1 < n) {
                __half2 h = __floats2half2_rn(acc[im][jn][2], acc[im][jn][3]);
                *(__half2*)&C[r1 * COUT + cc] = h;
            }
        }
    }
}

// ---------------- post (layers 2,3): h = relu(mean_agg(hl) + bl + hr), all fp16 in ----------
#define ACC8(v)                                              \
    do {                                                     \
        float2 _f;                                           \
        _f = __half22float2(*(__half2*)&(v).x); a0 += _f.x; a1 += _f.y; \
        _f = __half22float2(*(__half2*)&(v).y); a2 += _f.x; a3 += _f.y; \
        _f = __half22float2(*(__half2*)&(v).z); a4 += _f.x; a5 += _f.y; \
        _f = __half22float2(*(__half2*)&(v).w); a6 += _f.x; a7 += _f.y; \
    } while (0)

template <int D>
__global__ void k_post(const int* __restrict__ rowptr, const int* __restrict__ csrc,
                       const __half* __restrict__ hl, const __half* __restrict__ hr,
                       const float* __restrict__ bl, __half* __restrict__ hout, int n) {
    constexpr int LPN = D / 8;
    int tid = blockIdx.x * blockDim.x + threadIdx.x;
    int node = tid / LPN;
    int sub = tid % LPN;
    if (node >= n) return;
    int rs = rowptr[node], re = rowptr[node + 1];
    float a0 = 0.f, a1 = 0.f, a2 = 0.f, a3 = 0.f, a4 = 0.f, a5 = 0.f, a6 = 0.f, a7 = 0.f;
    int t = rs;
    for (; t + 1 < re; t += 2) {
        int s0 = csrc[t], s1 = csrc[t + 1];
        uint4 v0 = *(const uint4*)&hl[s0 * D + sub * 8];
        uint4 v1 = *(const uint4*)&hl[s1 * D + sub * 8];
        ACC8(v0); ACC8(v1);
    }
    if (t < re) {
        int s0 = csrc[t];
        uint4 v0 = *(const uint4*)&hl[s0 * D + sub * 8];
        ACC8(v0);
    }
    float dv = (float)(re - rs);
    float inv = 1.0f / fmaxf(dv, 1.0f);
    uint4 rv = *(const uint4*)&hr[node * D + sub * 8];
    float2 r01 = __half22float2(*(__half2*)&rv.x);
    float2 r23 = __half22float2(*(__half2*)&rv.y);
    float2 r45 = __half22float2(*(__half2*)&rv.z);
    float2 r67 = __half22float2(*(__half2*)&rv.w);
    float4 b0 = *(const float4*)&bl[sub * 8];
    float4 b1 = *(const float4*)&bl[sub * 8 + 4];
    float o0 = fmaxf(a0 * inv + b0.x + r01.x, 0.f);
    float o1 = fmaxf(a1 * inv + b0.y + r01.y, 0.f);
    float o2 = fmaxf(a2 * inv + b0.z + r23.x, 0.f);
    float o3 = fmaxf(a3 * inv + b0.w + r23.y, 0.f);
    float o4 = fmaxf(a4 * inv + b1.x + r45.x, 0.f);
    float o5 = fmaxf(a5 * inv + b1.y + r45.y, 0.f);
    float o6 = fmaxf(a6 * inv + b1.z + r67.x, 0.f);
    float o7 = fmaxf(a7 * inv + b1.w + r67.y, 0.f);
    __half2 p0 = __floats2half2_rn(o0, o1);
    __half2 p1 = __floats2half2_rn(o2, o3);
    __half2 p2 = __floats2half2_rn(o4, o5);
    __half2 p3 = __floats2half2_rn(o6, o7);
    uint4 ov;
    ov.x = *(unsigned*)&p0; ov.y = *(unsigned*)&p1;
    ov.z = *(unsigned*)&p2; ov.w = *(unsigned*)&p3;
    *(uint4*)&hout[node * D + sub * 8] = ov;
}

// ---------------- fused 32->32 SAGE layer (layers 4 & 5): gather + matvec in one kernel ----
// 128 nodes per block, 256 threads. Gather: 2 thr/node. Matvec: 8 subs x 4 nodes per thread.
template <bool HEAD>
__launch_bounds__(256, 4)
__global__ void k_sage32(const int* __restrict__ rowptr, const int* __restrict__ csrc,
                         const __half* __restrict__ hin,
                         const float* __restrict__ Wl, const float* __restrict__ bl,
                         const float* __restrict__ Wr,
                         const float* __restrict__ Wo, const float* __restrict__ bo,
                         __half* __restrict__ hout, float* __restrict__ out, int n) {
    __shared__ float sWl[1024];
    __shared__ float sWr[1024];
    __shared__ float sbl[32];
    __shared__ float sWo[32];
    __shared__ float sAgg[128][33];
    __shared__ float sSelf[128][33];
    int tid = threadIdx.x;
    for (int i = tid; i < 1024; i += 256) { sWl[i] = Wl[i]; sWr[i] = Wr[i]; }
    if (tid < 32) { sbl[tid] = bl[tid]; sWo[tid] = HEAD ? Wo[tid] : 0.f; }

    int node0 = blockIdx.x * 128;
    {
        int local = tid >> 1;
        int hh = tid & 1;          // which 16-dim half
        int node = node0 + local;
        if (node < n) {
            int rs = rowptr[node], re = rowptr[node + 1];
            float a0 = 0.f, a1 = 0.f, a2 = 0.f, a3 = 0.f, a4 = 0.f, a5 = 0.f, a6 = 0.f, a7 = 0.f;
            float a8 = 0.f, a9 = 0.f, aa = 0.f, ab = 0.f, ac = 0.f, ad = 0.f, ae = 0.f, af = 0.f;
            const __half* basep = hin + hh * 16;
            for (int t = rs; t < re; t++) {
                int s0 = csrc[t];
                uint4 va = *(const uint4*)&basep[s0 * 32];
                uint4 vb = *(const uint4*)&basep[s0 * 32 + 8];
                float2 f;
                f = __half22float2(*(__half2*)&va.x); a0 += f.x; a1 += f.y;
                f = __half22float2(*(__half2*)&va.y); a2 += f.x; a3 += f.y;
                f = __half22float2(*(__half2*)&va.z); a4 += f.x; a5 += f.y;
                f = __half22float2(*(__half2*)&va.w); a6 += f.x; a7 += f.y;
                f = __half22float2(*(__half2*)&vb.x); a8 += f.x; a9 += f.y;
                f = __half22float2(*(__half2*)&vb.y); aa += f.x; ab += f.y;
                f = __half22float2(*(__half2*)&vb.z); ac += f.x; ad += f.y;
                f = __half22float2(*(__half2*)&vb.w); ae += f.x; af += f.y;
            }
            float inv = 1.0f / fmaxf((float)(re - rs), 1.0f);
            float* Ag = &sAgg[local][hh * 16];
            Ag[0] = a0 * inv; Ag[1] = a1 * inv; Ag[2] = a2 * inv; Ag[3] = a3 * inv;
            Ag[4] = a4 * inv; Ag[5] = a5 * inv; Ag[6] = a6 * inv; Ag[7] = a7 * inv;
            Ag[8] = a8 * inv; Ag[9] = a9 * inv; Ag[10] = aa * inv; Ag[11] = ab * inv;
            Ag[12] = ac * inv; Ag[13] = ad * inv; Ag[14] = ae * inv; Ag[15] = af * inv;
            uint4 sa = *(const uint4*)&basep[node * 32];
            uint4 sb = *(const uint4*)&basep[node * 32 + 8];
            float* Sf = &sSelf[local][hh * 16];
            float2 f;
            f = __half22float2(*(__half2*)&sa.x); Sf[0] = f.x; Sf[1] = f.y;
            f = __half22float2(*(__half2*)&sa.y); Sf[2] = f.x; Sf[3] = f.y;
            f = __half22float2(*(__half2*)&sa.z); Sf[4] = f.x; Sf[5] = f.y;
            f = __half22float2(*(__half2*)&sa.w); Sf[6] = f.x; Sf[7] = f.y;
            f = __half22float2(*(__half2*)&sb.x); Sf[8] = f.x; Sf[9] = f.y;
            f = __half22float2(*(__half2*)&sb.y); Sf[10] = f.x; Sf[11] = f.y;
            f = __half22float2(*(__half2*)&sb.z); Sf[12] = f.x; Sf[13] = f.y;
            f = __half22float2(*(__half2*)&sb.w); Sf[14] = f.x; Sf[15] = f.y;
        }
    }
    __syncthreads();

    // matvec: thread handles 4 nodes x 4 output dims
    int ng = tid >> 3, sub = tid & 7;
    int j0 = sub * 4;
    int lbase = ng * 4;
    float o[4][4];
#pragma unroll
    for (int nn = 0; nn < 4; nn++)
#pragma unroll
        for (int jj = 0; jj < 4; jj++) o[nn][jj] = sbl[j0 + jj];
#pragma unroll 8
    for (int k = 0; k < 32; k++) {
        float4 wl = *(const float4*)&sWl[k * 32 + j0];
        float4 wr = *(const float4*)&sWr[k * 32 + j0];
#pragma unroll
        for (int nn = 0; nn < 4; nn++) {
            float a = sAgg[lbase + nn][k];
            float sf = sSelf[lbase + nn][k];
            o[nn][0] += a * wl.x + sf * wr.x;
            o[nn][1] += a * wl.y + sf * wr.y;
            o[nn][2] += a * wl.z + sf * wr.z;
            o[nn][3] += a * wl.w + sf * wr.w;
        }
    }
#pragma unroll
    for (int nn = 0; nn < 4; nn++) {
        int node = node0 + lbase + nn;
        float r0 = fmaxf(o[nn][0], 0.f), r1 = fmaxf(o[nn][1], 0.f);
        float r2 = fmaxf(o[nn][2], 0.f), r3 = fmaxf(o[nn][3], 0.f);
        if (!HEAD) {
            if (node < n) {
                __half2 p0 = __floats2half2_rn(r0, r1);
                __half2 p1 = __floats2half2_rn(r2, r3);
                uint2 v;
                v.x = *(unsigned*)&p0; v.y = *(unsigned*)&p1;
                *(uint2*)&hout[node * 32 + j0] = v;
            }
        } else {
            float p = r0 * sWo[j0] + r1 * sWo[j0 + 1] + r2 * sWo[j0 + 2] + r3 * sWo[j0 + 3];
            p += __shfl_xor_sync(0xffffffffu, p, 1);
            p += __shfl_xor_sync(0xffffffffu, p, 2);
            p += __shfl_xor_sync(0xffffffffu, p, 4);
            if (sub == 0 && node < n) out[node] = p + bo[0];
        }
    }
}

// ---------------- launch ----------------
extern "C" void kernel_launch(void* const* d_in, const int* in_sizes, int n_in,
                              void* d_out, int out_size) {
    const float* x   = (const float*)d_in[0];
    const int*   ei  = (const int*)d_in[1];
    const float* Wl1 = (const float*)d_in[3];
    const float* bl1 = (const float*)d_in[4];
    const float* Wr1 = (const float*)d_in[5];
    const float* Wl2 = (const float*)d_in[6];
    const float* bl2 = (const float*)d_in[7];
    const float* Wr2 = (const float*)d_in[8];
    const float* Wl3 = (const float*)d_in[9];
    const float* bl3 = (const float*)d_in[10];
    const float* Wr3 = (const float*)d_in[11];
    const float* Wl4 = (const float*)d_in[12];
    const float* bl4 = (const float*)d_in[13];
    const float* Wr4 = (const float*)d_in[14];
    const float* Wl5 = (const float*)d_in[15];
    const float* bl5 = (const float*)d_in[16];
    const float* Wr5 = (const float*)d_in[17];
    const float* Wo  = (const float*)d_in[18];
    const float* bo  = (const float*)d_in[19];
    float* out = (float*)d_out;

    int n = in_sizes[0] / 2;
    int E = in_sizes[1] / 2;

    __half *p_h, *p_hl, *p_hr, *p_w2, *p_w3;
    int *p_cnt, *p_rowptr, *p_cursor, *p_csrc;
    unsigned* p_state;
    cudaGetSymbolAddress((void**)&p_h, g_h);
    cudaGetSymbolAddress((void**)&p_hl, g_hl);
    cudaGetSymbolAddress((void**)&p_hr, g_hr);
    cudaGetSymbolAddress((void**)&p_w2, g_w2);
    cudaGetSymbolAddress((void**)&p_w3, g_w3);
    cudaGetSymbolAddress((void**)&p_cnt, g_cnt);
    cudaGetSymbolAddress((void**)&p_rowptr, g_rowptr);
    cudaGetSymbolAddress((void**)&p_cursor, g_cursor);
    cudaGetSymbolAddress((void**)&p_csrc, g_csrc);
    cudaGetSymbolAddress((void**)&p_state, g_state);

    cudaFuncSetAttribute(k_gemm_mma<128, 128, 64>, cudaFuncAttributeMaxDynamicSharedMemorySize, 102400);
    cudaFuncSetAttribute(k_gemm_mma<128, 32, 32>,  cudaFuncAttributeMaxDynamicSharedMemorySize, 53248);

    int NB = (n + 1023) / 1024;
    int eg = (E + 255) / 256;
    int gb = (n + 127) / 128;
    int g_warp = (n * 32 + 255) / 256;
    int g_16   = (n * 16 + 255) / 256;
    int g_4    = (n * 4 + 255) / 256;
    int g_s32  = (n + 127) / 128;

    // CSR build (+weight pack +state zero folded into k_count)
    cudaMemsetAsync(p_cnt, 0, n * sizeof(int));
    k_count<<<eg, 256>>>(ei, p_cnt, E, Wl2, Wr2, Wl3, Wr3, p_w2, p_w3, p_state);
    k_scan_lb<<<NB, 256>>>(p_cnt, p_state, p_rowptr, p_cursor, n);
    k_fill<<<eg, 256>>>(ei, p_cursor, p_csrc, E);

    // layer 1 (2 -> 128)
    k_layer1<<<g_warp, 256>>>(x, p_rowptr, p_csrc, Wl1, bl1, Wr1, p_h, n);

    // layer 2 (128 -> 128)
    k_gemm_mma<128, 128, 64><<<gb, 512, 102400>>>(p_h, p_w2, p_hl, p_hr, n);
    k_post<128><<<g_16, 256>>>(p_rowptr, p_csrc, p_hl, p_hr, bl2, p_h, n);

    // layer 3 (128 -> 32)
    k_gemm_mma<128, 32, 32><<<gb, 256, 53248>>>(p_h, p_w3, p_hl, p_hr, n);
    k_post<32><<<g_4, 256>>>(p_rowptr, p_csrc, p_hl, p_hr, bl3, p_h, n);

    // layer 4 (32 -> 32) fused gather+matvec
    k_sage32<false><<<g_s32, 256>>>(p_rowptr, p_csrc, p_h, Wl4, bl4, Wr4,
                                    nullptr, nullptr, p_hl, nullptr, n);
    // layer 5 (32 -> 32) fused + output head (reads layer4 output from p_hl)
    k_sage32<true><<<g_s32, 256>>>(p_rowptr, p_csrc, p_hl, Wl5, bl5, Wr5,
                                   Wo, bo, nullptr, out, n);
}

// round 6
// speedup vs baseline: 1.0455x; 1.0455x over previous
#include <cuda_runtime.h>
#include <cuda_fp16.h>
#include <cstdint>

#define NN 100000
#define NE 1600000

// ---------------- scratch ----------------
__device__ __half g_h [NN * 128];   // node features fp16
__device__ __half g_hl[NN * 128];   // h @ Wl fp16 (gathered operand)
__device__ __half g_hr[NN * 128];   // h @ Wr fp16 (skip path)
__device__ float  g_aggx[2 * NN];   // layer-1 neighbor sum of x (edge atomics)
__device__ __half g_w2[128 * 256];  // packed fp16 [K][Wl|Wr]
__device__ __half g_w3[128 * 64];
__device__ __half g_w4[32 * 64];
__device__ __half g_w5[32 * 64];
__device__ int    g_cnt[NN];
__device__ int    g_rowptr[NN + 1];
__device__ int    g_cursor[NN];
__device__ int    g_csrc[NE];
__device__ unsigned g_state[128];   // lookback scan state

// ---------------- mma helpers ----------------
__device__ __forceinline__ uint32_t smem_u32(const void* p) {
    return (uint32_t)__cvta_generic_to_shared(p);
}
__device__ __forceinline__ void ldsm_x4(uint32_t& r0, uint32_t& r1, uint32_t& r2, uint32_t& r3, uint32_t a) {
    asm volatile("ldmatrix.sync.aligned.m8n8.x4.shared.b16 {%0,%1,%2,%3},[%4];"
                 : "=r"(r0), "=r"(r1), "=r"(r2), "=r"(r3) : "r"(a));
}
__device__ __forceinline__ void ldsm_x2t(uint32_t& r0, uint32_t& r1, uint32_t a) {
    asm volatile("ldmatrix.sync.aligned.m8n8.x2.trans.shared.b16 {%0,%1},[%2];"
                 : "=r"(r0), "=r"(r1) : "r"(a));
}
__device__ __forceinline__ void mma16816(float* c, uint32_t a0, uint32_t a1, uint32_t a2, uint32_t a3,
                                         uint32_t b0, uint32_t b1) {
    asm volatile("mma.sync.aligned.m16n8k16.row.col.f32.f16.f16.f32 "
                 "{%0,%1,%2,%3},{%4,%5,%6,%7},{%8,%9},{%0,%1,%2,%3};"
                 : "+f"(c[0]), "+f"(c[1]), "+f"(c[2]), "+f"(c[3])
                 : "r"(a0), "r"(a1), "r"(a2), "r"(a3), "r"(b0), "r"(b1));
}

// ---------------- count + weight pack + zero state/aggx (one kernel) ----------------
__global__ void k_count(const int* __restrict__ ei, int* __restrict__ cnt, int E,
                        const float* Wl2, const float* Wr2, const float* Wl3, const float* Wr3,
                        const float* Wl4, const float* Wr4, const float* Wl5, const float* Wr5,
                        __half* w2, __half* w3, __half* w4, __half* w5,
                        unsigned* state, float* aggx, int n) {
    int e = blockIdx.x * blockDim.x + threadIdx.x;
    if (e < E) atomicAdd(&cnt[ei[E + e]], 1);
    if (blockIdx.x == 0 && threadIdx.x < 128) state[threadIdx.x] = 0u;
    if (e < 2 * n) aggx[e] = 0.f;
    int i = e;
    if (i < 32768) {
        int k = i / 256, j = i % 256;
        float v = (j < 128) ? Wl2[k * 128 + j] : Wr2[k * 128 + j - 128];
        w2[i] = __float2half_rn(v);
    } else if (i < 40960) {
        int q = i - 32768;
        int k = q / 64, j = q % 64;
        float v = (j < 32) ? Wl3[k * 32 + j] : Wr3[k * 32 + j - 32];
        w3[q] = __float2half_rn(v);
    } else if (i < 43008) {
        int q = i - 40960;
        int k = q / 64, j = q % 64;
        float v = (j < 32) ? Wl4[k * 32 + j] : Wr4[k * 32 + j - 32];
        w4[q] = __float2half_rn(v);
    } else if (i < 45056) {
        int q = i - 43008;
        int k = q / 64, j = q % 64;
        float v = (j < 32) ? Wl5[k * 32 + j] : Wr5[k * 32 + j - 32];
        w5[q] = __float2half_rn(v);
    }
}

// ---------------- decoupled-lookback exclusive scan ----------------
__global__ void k_scan_lb(const int* __restrict__ cnt, volatile unsigned* state,
                          int* __restrict__ rowptr, int* __restrict__ cursor, int n) {
    __shared__ int ws[8];
    __shared__ int s_pref;
    int bid = blockIdx.x;
    int base = bid * 1024 + threadIdx.x * 4;
    int c[4];
#pragma unroll
    for (int q = 0; q < 4; q++) { int idx = base + q; c[q] = (idx < n) ? cnt[idx] : 0; }
    int s1 = c[0], s2 = s1 + c[1], s3 = s2 + c[2], s4 = s3 + c[3];
    int lane = threadIdx.x & 31, w = threadIdx.x >> 5;
    int v = s4;
#pragma unroll
    for (int d = 1; d < 32; d <<= 1) {
        int u = __shfl_up_sync(0xffffffffu, v, d);
        if (lane >= d) v += u;
    }
    int texcl = v - s4;
    if (lane == 31) ws[w] = v;
    __syncthreads();
    if (threadIdx.x == 0) {
        int run = 0;
#pragma unroll
        for (int i = 0; i < 8; i++) { int t = ws[i]; ws[i] = run; run += t; }
        if (bid == 0) {
            state[0] = ((unsigned)run << 2) | 2u;
            __threadfence();
            s_pref = 0;
        } else {
            state[bid] = ((unsigned)run << 2) | 1u;
            __threadfence();
            int pref = 0;
            int j = bid - 1;
            while (true) {
                unsigned st = state[j];
                unsigned mode = st & 3u;
                if (mode == 0u) { __nanosleep(20); continue; }
                pref += (int)(st >> 2);
                if (mode == 2u) break;
                j--;
            }
            state[bid] = ((unsigned)(pref + run) << 2) | 2u;
            __threadfence();
            s_pref = pref;
        }
    }
    __syncthreads();
    int ofs = s_pref + ws[w] + texcl;
    int sv[4] = {s1, s2, s3, s4};
#pragma unroll
    for (int q = 0; q < 4; q++) {
        int idx = base + q;
        if (idx < n) {
            int val = ofs + sv[q];
            rowptr[idx + 1] = val;
            cursor[idx] = val - c[q];
        }
    }
    if (bid == 0 && threadIdx.x == 0) rowptr[0] = 0;
}

// ---------------- fill CSR + layer-1 dim-2 aggregation via edge atomics ----------------
__global__ void k_fill(const int* __restrict__ ei, const float* __restrict__ x,
                       int* __restrict__ cursor, int* __restrict__ csrc,
                       float* __restrict__ aggx, int E) {
    int e = blockIdx.x * blockDim.x + threadIdx.x;
    if (e < E) {
        int s = ei[e], d = ei[E + e];
        int p = atomicAdd(&cursor[d], 1);
        csrc[p] = s;
        float2 xv = *(const float2*)&x[2 * s];
        atomicAdd(&aggx[2 * d], xv.x);
        atomicAdd(&aggx[2 * d + 1], xv.y);
    }
}

// ---------------- layer 1 compute-only: h1 = relu([agg | x] @ W + b), fp16 out ----------
__global__ void k_layer1c(const float* __restrict__ x, const float* __restrict__ aggx,
                          const int* __restrict__ rowptr,
                          const float* __restrict__ Wl, const float* __restrict__ bl,
                          const float* __restrict__ Wr,
                          __half* __restrict__ hout, int n) {
    __shared__ float sWl[256], sWr[256], sbl[128];
    for (int i = threadIdx.x; i < 256; i += blockDim.x) { sWl[i] = Wl[i]; sWr[i] = Wr[i]; }
    for (int i = threadIdx.x; i < 128; i += blockDim.x) sbl[i] = bl[i];
    __syncthreads();
    int gt = blockIdx.x * blockDim.x + threadIdx.x;
    int node = gt >> 5;
    int lane = gt & 31;
    if (node >= n) return;
    float deg = (float)(rowptr[node + 1] - rowptr[node]);
    float inv = 1.0f / fmaxf(deg, 1.0f);
    float ax = aggx[2 * node] * inv;
    float ay = aggx[2 * node + 1] * inv;
    float2 xv = *(const float2*)&x[2 * node];
    int j = lane * 4;
    float o0 = fmaxf(ax * sWl[j + 0] + ay * sWl[128 + j + 0] + sbl[j + 0] + xv.x * sWr[j + 0] + xv.y * sWr[128 + j + 0], 0.f);
    float o1 = fmaxf(ax * sWl[j + 1] + ay * sWl[128 + j + 1] + sbl[j + 1] + xv.x * sWr[j + 1] + xv.y * sWr[128 + j + 1], 0.f);
    float o2 = fmaxf(ax * sWl[j + 2] + ay * sWl[128 + j + 2] + sbl[j + 2] + xv.x * sWr[j + 2] + xv.y * sWr[128 + j + 2], 0.f);
    float o3 = fmaxf(ax * sWl[j + 3] + ay * sWl[128 + j + 3] + sbl[j + 3] + xv.x * sWr[j + 3] + xv.y * sWr[128 + j + 3], 0.f);
    __half2 p0 = __floats2half2_rn(o0, o1);
    __half2 p1 = __floats2half2_rn(o2, o3);
    uint2 v;
    v.x = *(unsigned*)&p0; v.y = *(unsigned*)&p1;
    *(uint2*)&hout[node * 128 + j] = v;
}

// ---------------- tensor-core GEMM: [Cl | Cr] both fp16 ----------------
template <int K, int COUT, int WN>
__global__ void k_gemm_mma(const __half* __restrict__ A, const __half* __restrict__ W,
                           __half* __restrict__ Cl, __half* __restrict__ Cr, int n) {
    constexpr int BN = 2 * COUT;
    constexpr int NWN = BN / WN;
    constexpr int NW = 4 * NWN;
    constexpr int THREADS = NW * 32;
    constexpr int LDA = K + 8;
    constexpr int LDB = BN + 8;
    constexpr int NFN = WN / 8;
    extern __shared__ __half sm[];
    __half* As = sm;
    __half* Bs = sm + 128 * LDA;
    int tid = threadIdx.x;
    int row0 = blockIdx.x * 128;

    for (int i = tid; i < K * BN / 8; i += THREADS) {
        int f = i * 8;
        int k = f / BN, j = f % BN;
        *(uint4*)&Bs[k * LDB + j] = *(const uint4*)&W[f];
    }
    for (int i = tid; i < 128 * K / 8; i += THREADS) {
        int f = i * 8;
        int m = f / K, k = f % K;
        int row = row0 + m;
        uint4 v = make_uint4(0u, 0u, 0u, 0u);
        if (row < n) v = *(const uint4*)&A[row * K + k];
        *(uint4*)&As[m * LDA + k] = v;
    }
    __syncthreads();

    int wid = tid >> 5, lane = tid & 31;
    int wm = wid & 3, wn = wid >> 2;
    int m_base = wm * 32, n_base = wn * WN;

    float acc[2][NFN][4];
#pragma unroll
    for (int im = 0; im < 2; im++)
#pragma unroll
        for (int jn = 0; jn < NFN; jn++)
#pragma unroll
            for (int q = 0; q < 4; q++) acc[im][jn][q] = 0.f;

    int lr = lane & 15, lc = lane >> 4;
    uint32_t a_base0 = smem_u32(&As[(m_base + lr) * LDA]);
    uint32_t a_base1 = smem_u32(&As[(m_base + 16 + lr) * LDA]);
    uint32_t b_base = smem_u32(&Bs[lr * LDB + n_base]);

#pragma unroll
    for (int k0 = 0; k0 < K; k0 += 16) {
        uint32_t af[2][4];
        ldsm_x4(af[0][0], af[0][1], af[0][2], af[0][3], a_base0 + (k0 + lc * 8) * 2);
        ldsm_x4(af[1][0], af[1][1], af[1][2], af[1][3], a_base1 + (k0 + lc * 8) * 2);
        uint32_t bf[NFN][2];
#pragma unroll
        for (int jn = 0; jn < NFN; jn++)
            ldsm_x2t(bf[jn][0], bf[jn][1], b_base + (k0 * LDB + jn * 8) * 2);
#pragma unroll
        for (int im = 0; im < 2; im++)
#pragma unroll
            for (int jn = 0; jn < NFN; jn++)
                mma16816(acc[im][jn], af[im][0], af[im][1], af[im][2], af[im][3],
                         bf[jn][0], bf[jn][1]);
    }

    int quad = lane >> 2, t4 = lane & 3;
#pragma unroll
    for (int im = 0; im < 2; im++) {
#pragma unroll
        for (int jn = 0; jn < NFN; jn++) {
            int col = n_base + jn * 8 + t4 * 2;
            int r0 = row0 + m_base + im * 16 + quad;
            int r1 = r0 + 8;
            __half* C;
            int cc;
            if (col < COUT) { C = Cl; cc = col; }
            else            { C = Cr; cc = col - COUT; }
            if (r0 < n) {
                __half2 h = __floats2half2_rn(acc[im][jn][0], acc[im][jn][1]);
                *(__half2*)&C[r0 * COUT + cc] = h;
            }
            if (r1 < n) {
                __half2 h = __floats2half2_rn(acc[im][jn][2], acc[im][jn][3]);
                *(__half2*)&C[r1 * COUT + cc] = h;
            }
        }
    }
}

// ---------------- post: h = relu(mean_agg(hl) + bl + hr), unroll-4 gather ----------------
#define ACC8(v)                                              \
    do {                                                     \
        float2 _f;                                           \
        _f = __half22float2(*(__half2*)&(v).x); a0 += _f.x; a1 += _f.y; \
        _f = __half22float2(*(__half2*)&(v).y); a2 += _f.x; a3 += _f.y; \
        _f = __half22float2(*(__half2*)&(v).z); a4 += _f.x; a5 += _f.y; \
        _f = __half22float2(*(__half2*)&(v).w); a6 += _f.x; a7 += _f.y; \
    } while (0)

template <int D>
__global__ void k_post(const int* __restrict__ rowptr, const int* __restrict__ csrc,
                       const __half* __restrict__ hl, const __half* __restrict__ hr,
                       const float* __restrict__ bl, __half* __restrict__ hout, int n) {
    constexpr int LPN = D / 8;
    int tid = blockIdx.x * blockDim.x + threadIdx.x;
    int node = tid / LPN;
    int sub = tid % LPN;
    if (node >= n) return;
    int rs = rowptr[node], re = rowptr[node + 1];
    float a0 = 0.f, a1 = 0.f, a2 = 0.f, a3 = 0.f, a4 = 0.f, a5 = 0.f, a6 = 0.f, a7 = 0.f;
    int t = rs;
    for (; t + 3 < re; t += 4) {
        int s0 = csrc[t], s1 = csrc[t + 1], s2 = csrc[t + 2], s3 = csrc[t + 3];
        uint4 v0 = *(const uint4*)&hl[s0 * D + sub * 8];
        uint4 v1 = *(const uint4*)&hl[s1 * D + sub * 8];
        uint4 v2 = *(const uint4*)&hl[s2 * D + sub * 8];
        uint4 v3 = *(const uint4*)&hl[s3 * D + sub * 8];
        ACC8(v0); ACC8(v1); ACC8(v2); ACC8(v3);
    }
    for (; t < re; t++) {
        int s0 = csrc[t];
        uint4 v0 = *(const uint4*)&hl[s0 * D + sub * 8];
        ACC8(v0);
    }
    float dv = (float)(re - rs);
    float inv = 1.0f / fmaxf(dv, 1.0f);
    uint4 rv = *(const uint4*)&hr[node * D + sub * 8];
    float2 r01 = __half22float2(*(__half2*)&rv.x);
    float2 r23 = __half22float2(*(__half2*)&rv.y);
    float2 r45 = __half22float2(*(__half2*)&rv.z);
    float2 r67 = __half22float2(*(__half2*)&rv.w);
    float4 b0 = *(const float4*)&bl[sub * 8];
    float4 b1 = *(const float4*)&bl[sub * 8 + 4];
    float o0 = fmaxf(a0 * inv + b0.x + r01.x, 0.f);
    float o1 = fmaxf(a1 * inv + b0.y + r01.y, 0.f);
    float o2 = fmaxf(a2 * inv + b0.z + r23.x, 0.f);
    float o3 = fmaxf(a3 * inv + b0.w + r23.y, 0.f);
    float o4 = fmaxf(a4 * inv + b1.x + r45.x, 0.f);
    float o5 = fmaxf(a5 * inv + b1.y + r45.y, 0.f);
    float o6 = fmaxf(a6 * inv + b1.z + r67.x, 0.f);
    float o7 = fmaxf(a7 * inv + b1.w + r67.y, 0.f);
    __half2 p0 = __floats2half2_rn(o0, o1);
    __half2 p1 = __floats2half2_rn(o2, o3);
    __half2 p2 = __floats2half2_rn(o4, o5);
    __half2 p3 = __floats2half2_rn(o6, o7);
    uint4 ov;
    ov.x = *(unsigned*)&p0; ov.y = *(unsigned*)&p1;
    ov.z = *(unsigned*)&p2; ov.w = *(unsigned*)&p3;
    *(uint4*)&hout[node * D + sub * 8] = ov;
}

// ---------------- layer 5 post fused with output head ----------------
__global__ void k_post_out(const int* __restrict__ rowptr, const int* __restrict__ csrc,
                           const __half* __restrict__ hl, const __half* __restrict__ hr,
                           const float* __restrict__ bl,
                           const float* __restrict__ Wo, const float* __restrict__ bo,
                           float* __restrict__ out, int n) {
    constexpr int D = 32;
    constexpr int LPN = 4;
    int tid = blockIdx.x * blockDim.x + threadIdx.x;
    int node = tid / LPN;
    int sub = tid % LPN;
    if (node >= n) return;
    int rs = rowptr[node], re = rowptr[node + 1];
    float a0 = 0.f, a1 = 0.f, a2 = 0.f, a3 = 0.f, a4 = 0.f, a5 = 0.f, a6 = 0.f, a7 = 0.f;
    int t = rs;
    for (; t + 3 < re; t += 4) {
        int s0 = csrc[t], s1 = csrc[t + 1], s2 = csrc[t + 2], s3 = csrc[t + 3];
        uint4 v0 = *(const uint4*)&hl[s0 * D + sub * 8];
        uint4 v1 = *(const uint4*)&hl[s1 * D + sub * 8];
        uint4 v2 = *(const uint4*)&hl[s2 * D + sub * 8];
        uint4 v3 = *(const uint4*)&hl[s3 * D + sub * 8];
        ACC8(v0); ACC8(v1); ACC8(v2); ACC8(v3);
    }
    for (; t < re; t++) {
        int s0 = csrc[t];
        uint4 v0 = *(const uint4*)&hl[s0 * D + sub * 8];
        ACC8(v0);
    }
    float dv = (float)(re - rs);
    float inv = 1.0f / fmaxf(dv, 1.0f);
    uint4 rv = *(const uint4*)&hr[node * D + sub * 8];
    float2 r01 = __half22float2(*(__half2*)&rv.x);
    float2 r23 = __half22float2(*(__half2*)&rv.y);
    float2 r45 = __half22float2(*(__half2*)&rv.z);
    float2 r67 = __half22float2(*(__half2*)&rv.w);
    float4 b0 = *(const float4*)&bl[sub * 8];
    float4 b1 = *(const float4*)&bl[sub * 8 + 4];
    float4 w0 = *(const float4*)&Wo[sub * 8];
    float4 w1 = *(const float4*)&Wo[sub * 8 + 4];
    float s = 0.f;
    s += fmaxf(a0 * inv + b0.x + r01.x, 0.f) * w0.x;
    s += fmaxf(a1 * inv + b0.y + r01.y, 0.f) * w0.y;
    s += fmaxf(a2 * inv + b0.z + r23.x, 0.f) * w0.z;
    s += fmaxf(a3 * inv + b0.w + r23.y, 0.f) * w0.w;
    s += fmaxf(a4 * inv + b1.x + r45.x, 0.f) * w1.x;
    s += fmaxf(a5 * inv + b1.y + r45.y, 0.f) * w1.y;
    s += fmaxf(a6 * inv + b1.z + r67.x, 0.f) * w1.z;
    s += fmaxf(a7 * inv + b1.w + r67.y, 0.f) * w1.w;
    s += __shfl_xor_sync(0xffffffffu, s, 1);
    s += __shfl_xor_sync(0xffffffffu, s, 2);
    if (sub == 0) out[node] = s + bo[0];
}

// ---------------- launch ----------------
extern "C" void kernel_launch(void* const* d_in, const int* in_sizes, int n_in,
                              void* d_out, int out_size) {
    const float* x   = (const float*)d_in[0];
    const int*   ei  = (const int*)d_in[1];
    const float* Wl1 = (const float*)d_in[3];
    const float* bl1 = (const float*)d_in[4];
    const float* Wr1 = (const float*)d_in[5];
    const float* Wl2 = (const float*)d_in[6];
    const float* bl2 = (const float*)d_in[7];
    const float* Wr2 = (const float*)d_in[8];
    const float* Wl3 = (const float*)d_in[9];
    const float* bl3 = (const float*)d_in[10];
    const float* Wr3 = (const float*)d_in[11];
    const float* Wl4 = (const float*)d_in[12];
    const float* bl4 = (const float*)d_in[13];
    const float* Wr4 = (const float*)d_in[14];
    const float* Wl5 = (const float*)d_in[15];
    const float* bl5 = (const float*)d_in[16];
    const float* Wr5 = (const float*)d_in[17];
    const float* Wo  = (const float*)d_in[18];
    const float* bo  = (const float*)d_in[19];
    float* out = (float*)d_out;

    int n = in_sizes[0] / 2;
    int E = in_sizes[1] / 2;

    __half *p_h, *p_hl, *p_hr, *p_w2, *p_w3, *p_w4, *p_w5;
    float* p_aggx;
    int *p_cnt, *p_rowptr, *p_cursor, *p_csrc;
    unsigned* p_state;
    cudaGetSymbolAddress((void**)&p_h, g_h);
    cudaGetSymbolAddress((void**)&p_hl, g_hl);
    cudaGetSymbolAddress((void**)&p_hr, g_hr);
    cudaGetSymbolAddress((void**)&p_aggx, g_aggx);
    cudaGetSymbolAddress((void**)&p_w2, g_w2);
    cudaGetSymbolAddress((void**)&p_w3, g_w3);
    cudaGetSymbolAddress((void**)&p_w4, g_w4);
    cudaGetSymbolAddress((void**)&p_w5, g_w5);
    cudaGetSymbolAddress((void**)&p_cnt, g_cnt);
    cudaGetSymbolAddress((void**)&p_rowptr, g_rowptr);
    cudaGetSymbolAddress((void**)&p_cursor, g_cursor);
    cudaGetSymbolAddress((void**)&p_csrc, g_csrc);
    cudaGetSymbolAddress((void**)&p_state, g_state);

    cudaFuncSetAttribute(k_gemm_mma<128, 128, 64>, cudaFuncAttributeMaxDynamicSharedMemorySize, 102400);
    cudaFuncSetAttribute(k_gemm_mma<128, 32, 32>,  cudaFuncAttributeMaxDynamicSharedMemorySize, 53248);
    cudaFuncSetAttribute(k_gemm_mma<32, 32, 32>,   cudaFuncAttributeMaxDynamicSharedMemorySize, 14848);

    int NB = (n + 1023) / 1024;
    int eg = (E + 255) / 256;
    int gb = (n + 127) / 128;
    int g_warp = (n * 32 + 255) / 256;
    int g_16   = (n * 16 + 255) / 256;
    int g_4    = (n * 4 + 255) / 256;

    // CSR build (+weight pack +zeroing folded into k_count; layer1 agg folded into k_fill)
    cudaMemsetAsync(p_cnt, 0, n * sizeof(int));
    k_count<<<eg, 256>>>(ei, p_cnt, E, Wl2, Wr2, Wl3, Wr3, Wl4, Wr4, Wl5, Wr5,
                         p_w2, p_w3, p_w4, p_w5, p_state, p_aggx, n);
    k_scan_lb<<<NB, 256>>>(p_cnt, p_state, p_rowptr, p_cursor, n);
    k_fill<<<eg, 256>>>(ei, x, p_cursor, p_csrc, p_aggx, E);

    // layer 1 (2 -> 128): compute only (agg already in p_aggx)
    k_layer1c<<<g_warp, 256>>>(x, p_aggx, p_rowptr, Wl1, bl1, Wr1, p_h, n);

    // layer 2 (128 -> 128)
    k_gemm_mma<128, 128, 64><<<gb, 512, 102400>>>(p_h, p_w2, p_hl, p_hr, n);
    k_post<128><<<g_16, 256>>>(p_rowptr, p_csrc, p_hl, p_hr, bl2, p_h, n);

    // layer 3 (128 -> 32)
    k_gemm_mma<128, 32, 32><<<gb, 256, 53248>>>(p_h, p_w3, p_hl, p_hr, n);
    k_post<32><<<g_4, 256>>>(p_rowptr, p_csrc, p_hl, p_hr, bl3, p_h, n);

    // layer 4 (32 -> 32)
    k_gemm_mma<32, 32, 32><<<gb, 256, 14848>>>(p_h, p_w4, p_hl, p_hr, n);
    k_post<32><<<g_4, 256>>>(p_rowptr, p_csrc, p_hl, p_hr, bl4, p_h, n);

    // layer 5 (32 -> 32) + fused output head
    k_gemm_mma<32, 32, 32><<<gb, 256, 14848>>>(p_h, p_w5, p_hl, p_hr, n);
    k_post_out<<<g_4, 256>>>(p_rowptr, p_csrc, p_hl, p_hr, bl5, Wo, bo, out, n);
}